// round 10
// baseline (speedup 1.0000x reference)
#include <cuda_runtime.h>
#include <cstdint>
#include <cstddef>

#define B_     128
#define T_     32
#define NCAT   32
#define MAXCH  80
#define BM     64
#define BN     128
#define BK     32
#define NT     64

#define A_STAGE_BYTES 8192                       // 64 rows x 32 k x 4B (swizzled)
#define B_STRIDE_W    136                        // 128 + 8 pad words (stride % 32 == 8)
#define B_STAGE_BYTES (32 * B_STRIDE_W * 4)      // 17408
#define STAGE_BYTES   (A_STAGE_BYTES + B_STAGE_BYTES)
#define SMEM_REQ      (2 * STAGE_BYTES)          // 51200

__device__ float g_hidden[B_ * T_ * 1024];       // 16 MB fp32 hidden scratch

__device__ __forceinline__ uint32_t f2tf32(float f) {
    uint32_t r;
    asm("cvt.rna.tf32.f32 %0, %1;" : "=r"(r) : "f"(f));
    return r;
}
__device__ __forceinline__ uint32_t smem_u32(const void* p) {
    uint32_t a;
    asm("{ .reg .u64 t; cvta.to.shared.u64 t, %1; cvt.u32.u64 %0, t; }" : "=r"(a) : "l"(p));
    return a;
}
__device__ __forceinline__ void cpa16(uint32_t d, const void* s) {
    asm volatile("cp.async.cg.shared.global [%0], [%1], 16;" :: "r"(d), "l"(s));
}

// ---------------------------------------------------------------------------
// One layer: out[chunk 64 rows x 128 n-tile] = act(A[64,K] @ W[cat][K,1024] + b)
// 64 threads = 2 fat warps (1M x 2N), warp tile 64x64, mma.sync.m16n8k8 tf32,
// register double-buffered fragments, 4 CTAs/SM (4 barrier domains).
// ---------------------------------------------------------------------------
template <int K, bool RELU, bool IN_S, bool OUT_S>
__global__ __launch_bounds__(NT, 4)
void catmlp_gemm(const float* __restrict__ gin, const float* __restrict__ Wt,
                 const float* __restrict__ bias, const int* __restrict__ cat_ids,
                 float* __restrict__ gout)
{
    extern __shared__ char smem[];
    const uint32_t sb = smem_u32(smem);

    __shared__ int cats[B_];
    __shared__ int s_cnt[NCAT], s_base[NCAT];
    __shared__ int s_cb[2], s_cat, s_nch;
    __shared__ const float* rowp[BM];

    const int tid  = threadIdx.x;
    const int wid  = tid >> 5;
    const int lane = tid & 31;
    const int bx   = blockIdx.x;

    // ---- per-CTA chunk decomposition (chunks = groups of <=2 same-cat batches) ----
    for (int t = tid; t < B_; t += NT) cats[t] = cat_ids[t];
    __syncthreads();
    if (wid == 0) {
        int n = 0;
        #pragma unroll 4
        for (int b = 0; b < B_; b++) n += (cats[b] == lane);
        int ch = (n + 1) >> 1;
        int inc = ch;
        #pragma unroll
        for (int d = 1; d < 32; d <<= 1) {
            int v = __shfl_up_sync(0xffffffffu, inc, d);
            if (lane >= d) inc += v;
        }
        s_cnt[lane]  = n;
        s_base[lane] = inc - ch;
        if (lane == 31) s_nch = inc;
        bool own = (bx >= inc - ch) && (bx < inc);
        uint32_t m = __ballot_sync(0xffffffffu, own);
        if (lane == 0) s_cat = m ? (__ffs(m) - 1) : 0;
    }
    __syncthreads();
    if (bx >= s_nch) return;

    const int cat = s_cat;
    const int jg  = bx - s_base[cat];
    const int ncc = s_cnt[cat];
    for (int t = tid; t < B_; t += NT) {
        if (cats[t] == cat) {
            int r = 0;
            for (int b = 0; b < t; b++) r += (cats[b] == cat);
            int nv = ncc - jg * 2;
            if (nv > 2) nv = 2;
            if (r >= jg * 2 && r < jg * 2 + 2) s_cb[r - jg * 2] = t;
            if (r == ncc - 1)
                for (int q = nv; q < 2; q++) s_cb[q] = t;  // pad by replication
        }
    }
    __syncthreads();

    const float* in_base = IN_S ? (const float*)g_hidden : gin;
    rowp[tid] = in_base + ((size_t)s_cb[tid >> 5] * T_ + (tid & 31)) * (size_t)K;
    const float* Wc = Wt + (size_t)cat * K * 1024;
    const int n0 = blockIdx.y * BN;
    __syncthreads();

    constexpr int NC = K / BK;

    auto stage = [&](int ch) {
        const int k0 = ch * BK;
        const uint32_t base = sb + (ch & 1) * STAGE_BYTES;
        #pragma unroll
        for (int j = 0; j < 8; j++) {             // A: 512 x 16B chunks / 64 thr
            int c   = tid + (j << 6);
            int row = c >> 3;
            int cw  = (c & 7) << 2;
            uint32_t dst = base + ((row << 5) + (cw ^ ((row & 7) << 2))) * 4;
            cpa16(dst, rowp[row] + k0 + cw);
        }
        const uint32_t bbase = base + A_STAGE_BYTES;
        #pragma unroll
        for (int j = 0; j < 16; j++) {            // B: 1024 x 16B chunks / 64 thr
            int c  = tid + (j << 6);
            int k  = c >> 5;                      // 32 x 16B per row
            int nw = (c & 31) << 2;
            uint32_t dst = bbase + (k * B_STRIDE_W + nw) * 4;
            cpa16(dst, Wc + (size_t)(k0 + k) * 1024 + n0 + nw);
        }
        asm volatile("cp.async.commit_group;" ::: "memory");
    };

    stage(0);
    stage(1);

    const int wn = wid * 64;                     // 0 / 64 (N warp)
    const int lg = lane >> 2;
    const int lr = lane & 3;
    const int sw = lg << 2;

    float acc[4][8][4];
    #pragma unroll
    for (int mf = 0; mf < 4; mf++)
        #pragma unroll
        for (int nf = 0; nf < 8; nf++)
            #pragma unroll
            for (int q = 0; q < 4; q++) acc[mf][nf][q] = 0.f;

    uint32_t ua[2][4][4];                        // [buf][mf][frag]
    uint32_t ub[2][8][2];                        // [buf][nf][frag]

    for (int i = 0; i < NC; i++) {
        if (i < NC - 1) asm volatile("cp.async.wait_group 1;" ::: "memory");
        else            asm volatile("cp.async.wait_group 0;" ::: "memory");
        __syncthreads();

        const char* sbuf = smem + (size_t)(i & 1) * STAGE_BYTES;
        const float* As = (const float*)sbuf;
        const float* Bs = (const float*)(sbuf + A_STAGE_BYTES);

        // prologue: ks=0 fragments -> buffer 0
        {
            const int c0 = lr ^ sw, c1 = c0 ^ 4;
            #pragma unroll
            for (int mf = 0; mf < 4; mf++) {
                const int r0 = mf * 16 + lg;
                ua[0][mf][0] = f2tf32(As[(r0    ) * 32 + c0]);
                ua[0][mf][1] = f2tf32(As[(r0 + 8) * 32 + c0]);
                ua[0][mf][2] = f2tf32(As[(r0    ) * 32 + c1]);
                ua[0][mf][3] = f2tf32(As[(r0 + 8) * 32 + c1]);
            }
            const int kb0 = lr * B_STRIDE_W, kb1 = kb0 + 4 * B_STRIDE_W;
            const int nb  = wn + lg;
            #pragma unroll
            for (int nf = 0; nf < 8; nf++) {
                ub[0][nf][0] = f2tf32(Bs[kb0 + nb + nf * 8]);
                ub[0][nf][1] = f2tf32(Bs[kb1 + nb + nf * 8]);
            }
        }

        #pragma unroll
        for (int ks = 0; ks < 4; ks++) {
            const int cur = ks & 1, nxt = cur ^ 1;
            if (ks < 3) {                         // load ks+1 while MMAing ks
                const int c0 = (((ks + 1) << 3) | lr) ^ sw, c1 = c0 ^ 4;
                #pragma unroll
                for (int mf = 0; mf < 4; mf++) {
                    const int r0 = mf * 16 + lg;
                    ua[nxt][mf][0] = f2tf32(As[(r0    ) * 32 + c0]);
                    ua[nxt][mf][1] = f2tf32(As[(r0 + 8) * 32 + c0]);
                    ua[nxt][mf][2] = f2tf32(As[(r0    ) * 32 + c1]);
                    ua[nxt][mf][3] = f2tf32(As[(r0 + 8) * 32 + c1]);
                }
                const int kb0 = (((ks + 1) << 3) + lr) * B_STRIDE_W;
                const int kb1 = kb0 + 4 * B_STRIDE_W;
                const int nb  = wn + lg;
                #pragma unroll
                for (int nf = 0; nf < 8; nf++) {
                    ub[nxt][nf][0] = f2tf32(Bs[kb0 + nb + nf * 8]);
                    ub[nxt][nf][1] = f2tf32(Bs[kb1 + nb + nf * 8]);
                }
            }
            #pragma unroll
            for (int mf = 0; mf < 4; mf++)
                #pragma unroll
                for (int nf = 0; nf < 8; nf++)
                    asm volatile(
                        "mma.sync.aligned.m16n8k8.row.col.f32.tf32.tf32.f32 "
                        "{%0,%1,%2,%3}, {%4,%5,%6,%7}, {%8,%9}, {%0,%1,%2,%3};"
                        : "+f"(acc[mf][nf][0]), "+f"(acc[mf][nf][1]),
                          "+f"(acc[mf][nf][2]), "+f"(acc[mf][nf][3])
                        : "r"(ua[cur][mf][0]), "r"(ua[cur][mf][1]),
                          "r"(ua[cur][mf][2]), "r"(ua[cur][mf][3]),
                          "r"(ub[cur][nf][0]), "r"(ub[cur][nf][1]));
        }

        __syncthreads();                          // all warps done with buffer i&1
        if (i + 2 < NC) stage(i + 2);             // refill; overlaps compute(i+1)
    }

    // ---- epilogue: +bias, optional ReLU, fp32 float2 stores ----
    float* ob = OUT_S ? (float*)g_hidden : gout;
    const float* brow = bias + (size_t)cat * 1024 + n0;
    float2 bb[8];
    #pragma unroll
    for (int nf = 0; nf < 8; nf++)
        bb[nf] = *(const float2*)(brow + wn + nf * 8 + lr * 2);

    #pragma unroll
    for (int mf = 0; mf < 4; mf++) {
        const int r0 = mf * 16 + lg;              // 0..63; rows 0-31 batch0, 32-63 batch1
        const int batch = s_cb[r0 >> 5];
        float* o0 = ob + ((size_t)batch * T_ + (r0 & 31)) * 1024 + n0;
        float* o1 = ob + ((size_t)batch * T_ + ((r0 + 8) & 31)) * 1024 + n0;
        #pragma unroll
        for (int nf = 0; nf < 8; nf++) {
            const int col = wn + nf * 8 + lr * 2;
            float2 v0, v1;
            v0.x = acc[mf][nf][0] + bb[nf].x;
            v0.y = acc[mf][nf][1] + bb[nf].y;
            v1.x = acc[mf][nf][2] + bb[nf].x;
            v1.y = acc[mf][nf][3] + bb[nf].y;
            if (RELU) {
                v0.x = fmaxf(v0.x, 0.f); v0.y = fmaxf(v0.y, 0.f);
                v1.x = fmaxf(v1.x, 0.f); v1.y = fmaxf(v1.y, 0.f);
            }
            *(float2*)(o0 + col) = v0;
            *(float2*)(o1 + col) = v1;
        }
    }
}

// ---------------------------------------------------------------------------
extern "C" void kernel_launch(void* const* d_in, const int* in_sizes, int n_in,
                              void* d_out, int out_size) {
    const float* x   = (const float*)d_in[0];
    const int*   cat = (const int*)  d_in[1];
    const float* W1  = (const float*)d_in[2];
    const float* b1  = (const float*)d_in[3];
    const float* W2  = (const float*)d_in[4];
    const float* b2  = (const float*)d_in[5];
    float*       out = (float*)d_out;

    cudaFuncSetAttribute(catmlp_gemm<1536, true,  false, true >,
                         cudaFuncAttributeMaxDynamicSharedMemorySize, SMEM_REQ);
    cudaFuncSetAttribute(catmlp_gemm<1024, false, true,  false>,
                         cudaFuncAttributeMaxDynamicSharedMemorySize, SMEM_REQ);

    dim3 grid(MAXCH, 1024 / BN);
    catmlp_gemm<1536, true,  false, true ><<<grid, NT, SMEM_REQ>>>(x,  W1, b1, cat, nullptr);
    catmlp_gemm<1024, false, true,  false><<<grid, NT, SMEM_REQ>>>(nullptr, W2, b2, cat, out);
}

// round 11
// speedup vs baseline: 1.4247x; 1.4247x over previous
#include <cuda_runtime.h>
#include <cstdint>
#include <cstddef>

#define B_     128
#define T_     32
#define NCAT   32
#define MAXCH  80
#define BM     64
#define BN     128
#define BK     32
#define NT     128

#define A_STAGE_BYTES 8192                       // 64 rows x 32 k x 4B (swizzled)
#define B_STRIDE_W    132                        // 128 + 4 pad words
#define B_STAGE_BYTES (32 * B_STRIDE_W * 4)      // 16896
#define STAGE_BYTES   (A_STAGE_BYTES + B_STAGE_BYTES)
#define SMEM_REQ      (2 * STAGE_BYTES)          // 50176

__device__ float g_hidden[B_ * T_ * 1024];       // 16 MB fp32 hidden scratch

__device__ __forceinline__ uint32_t smem_u32(const void* p) {
    uint32_t a;
    asm("{ .reg .u64 t; cvta.to.shared.u64 t, %1; cvt.u32.u64 %0, t; }" : "=r"(a) : "l"(p));
    return a;
}
__device__ __forceinline__ void cpa16(uint32_t d, const void* s) {
    asm volatile("cp.async.cg.shared.global [%0], [%1], 16;" :: "r"(d), "l"(s));
}
// pack {lo=f16(lo), hi=f16(hi)} -- first PTX source goes to the HIGH half
__device__ __forceinline__ uint32_t packh2(float lo, float hi) {
    uint32_t r;
    asm("cvt.rn.f16x2.f32 %0, %1, %2;" : "=r"(r) : "f"(hi), "f"(lo));
    return r;
}

// ---------------------------------------------------------------------------
// One layer: out[chunk 64 rows x 128 n-tile] = act(A[64,K] @ W[cat][K,1024] + b)
// 128 threads = 4 warps (2M x 2N), warp tile 32x64, mma.sync.m16n8k16 f16,
// fp32 staged in smem, converted to f16x2 at fragment load. 4 CTAs/SM.
// ---------------------------------------------------------------------------
template <int K, bool RELU, bool IN_S, bool OUT_S>
__global__ __launch_bounds__(NT, 4)
void catmlp_gemm(const float* __restrict__ gin, const float* __restrict__ Wt,
                 const float* __restrict__ bias, const int* __restrict__ cat_ids,
                 float* __restrict__ gout)
{
    extern __shared__ char smem[];
    const uint32_t sb = smem_u32(smem);

    __shared__ int cats[B_];
    __shared__ int s_cnt[NCAT], s_base[NCAT];
    __shared__ int s_cb[2], s_cat, s_nch;
    __shared__ const float* rowp[BM];

    const int tid  = threadIdx.x;
    const int wid  = tid >> 5;
    const int lane = tid & 31;
    const int bx   = blockIdx.x;

    // ---- per-CTA chunk decomposition (groups of <=2 same-cat batches) ----
    cats[tid] = cat_ids[tid];
    __syncthreads();
    if (wid == 0) {
        int n = 0;
        #pragma unroll 4
        for (int b = 0; b < B_; b++) n += (cats[b] == lane);
        int ch = (n + 1) >> 1;
        int inc = ch;
        #pragma unroll
        for (int d = 1; d < 32; d <<= 1) {
            int v = __shfl_up_sync(0xffffffffu, inc, d);
            if (lane >= d) inc += v;
        }
        s_cnt[lane]  = n;
        s_base[lane] = inc - ch;
        if (lane == 31) s_nch = inc;
        bool own = (bx >= inc - ch) && (bx < inc);
        uint32_t m = __ballot_sync(0xffffffffu, own);
        if (lane == 0) s_cat = m ? (__ffs(m) - 1) : 0;
    }
    __syncthreads();
    if (bx >= s_nch) return;

    const int cat = s_cat;
    const int jg  = bx - s_base[cat];
    const int ncc = s_cnt[cat];
    if (cats[tid] == cat) {
        int r = 0;
        for (int b = 0; b < tid; b++) r += (cats[b] == cat);
        int nv = ncc - jg * 2;
        if (nv > 2) nv = 2;
        if (r >= jg * 2 && r < jg * 2 + 2) s_cb[r - jg * 2] = tid;
        if (r == ncc - 1)
            for (int q = nv; q < 2; q++) s_cb[q] = tid;  // pad by replication
    }
    __syncthreads();

    const float* in_base = IN_S ? (const float*)g_hidden : gin;
    if (tid < BM) {
        int b = s_cb[tid >> 5];
        rowp[tid] = in_base + ((size_t)b * T_ + (tid & 31)) * (size_t)K;
    }
    const float* Wc = Wt + (size_t)cat * K * 1024;
    const int n0 = blockIdx.y * BN;
    __syncthreads();

    constexpr int NC = K / BK;

    auto stage = [&](int ch) {
        const int k0 = ch * BK;
        const uint32_t base = sb + (ch & 1) * STAGE_BYTES;
        #pragma unroll
        for (int j = 0; j < 4; j++) {             // A: 512 x 16B chunks / 128 thr
            int c   = tid + (j << 7);
            int row = c >> 3;
            int cw  = (c & 7) << 2;
            uint32_t dst = base + ((row << 5) + (cw ^ ((row & 3) << 3))) * 4;
            cpa16(dst, rowp[row] + k0 + cw);
        }
        const uint32_t bbase = base + A_STAGE_BYTES;
        #pragma unroll
        for (int j = 0; j < 8; j++) {             // B: 1024 x 16B chunks / 128 thr
            int c  = tid + (j << 7);
            int k  = c >> 5;                      // 32 x 16B per row
            int nw = (c & 31) << 2;
            uint32_t dst = bbase + (k * B_STRIDE_W + nw) * 4;
            cpa16(dst, Wc + (size_t)(k0 + k) * 1024 + n0 + nw);
        }
        asm volatile("cp.async.commit_group;" ::: "memory");
    };

    stage(0);
    stage(1);

    const int wm = (wid & 1) * 32;               // 0 / 32  (M warp)
    const int wn = (wid >> 1) * 64;              // 0 / 64  (N warp)
    const int lg = lane >> 2;                    // row within 8-group / n within 8
    const int lr = lane & 3;                     // k-pair selector
    const int swz = (lg & 3) << 3;               // A swizzle for this thread's rows

    float acc[2][8][4];
    #pragma unroll
    for (int mf = 0; mf < 2; mf++)
        #pragma unroll
        for (int nf = 0; nf < 8; nf++)
            #pragma unroll
            for (int q = 0; q < 4; q++) acc[mf][nf][q] = 0.f;

    for (int i = 0; i < NC; i++) {
        if (i < NC - 1) asm volatile("cp.async.wait_group 1;" ::: "memory");
        else            asm volatile("cp.async.wait_group 0;" ::: "memory");
        __syncthreads();

        const char* sbuf = smem + (size_t)(i & 1) * STAGE_BYTES;
        const float* As = (const float*)sbuf;
        const float* Bs = (const float*)(sbuf + A_STAGE_BYTES);

        #pragma unroll
        for (int ks = 0; ks < 2; ks++) {          // two K=16 steps per chunk
            const int cb = (ks << 4) + (lr << 1); // k col base (even)
            const int c0 = cb ^ swz;              // swizzle preserves bit0, flips bit3
            const int c1 = (cb + 8) ^ swz;
            uint32_t ua[2][4];
            #pragma unroll
            for (int mf = 0; mf < 2; mf++) {
                const int r0 = wm + mf * 16 + lg;
                float2 p00 = *(const float2*)(As + (r0    ) * 32 + c0);
                float2 p10 = *(const float2*)(As + (r0 + 8) * 32 + c0);
                float2 p01 = *(const float2*)(As + (r0    ) * 32 + c1);
                float2 p11 = *(const float2*)(As + (r0 + 8) * 32 + c1);
                ua[mf][0] = packh2(p00.x, p00.y);
                ua[mf][1] = packh2(p10.x, p10.y);
                ua[mf][2] = packh2(p01.x, p01.y);
                ua[mf][3] = packh2(p11.x, p11.y);
            }
            uint32_t ub[8][2];
            const int kr = (ks << 4) + (lr << 1);
            const int nb = wn + lg;
            #pragma unroll
            for (int nf = 0; nf < 8; nf++) {
                const int nn = nb + nf * 8;
                float f0 = Bs[(kr    ) * B_STRIDE_W + nn];
                float f1 = Bs[(kr + 1) * B_STRIDE_W + nn];
                float f2 = Bs[(kr + 8) * B_STRIDE_W + nn];
                float f3 = Bs[(kr + 9) * B_STRIDE_W + nn];
                ub[nf][0] = packh2(f0, f1);
                ub[nf][1] = packh2(f2, f3);
            }
            #pragma unroll
            for (int mf = 0; mf < 2; mf++)
                #pragma unroll
                for (int nf = 0; nf < 8; nf++)
                    asm volatile(
                        "mma.sync.aligned.m16n8k16.row.col.f32.f16.f16.f32 "
                        "{%0,%1,%2,%3}, {%4,%5,%6,%7}, {%8,%9}, {%0,%1,%2,%3};"
                        : "+f"(acc[mf][nf][0]), "+f"(acc[mf][nf][1]),
                          "+f"(acc[mf][nf][2]), "+f"(acc[mf][nf][3])
                        : "r"(ua[mf][0]), "r"(ua[mf][1]), "r"(ua[mf][2]), "r"(ua[mf][3]),
                          "r"(ub[nf][0]), "r"(ub[nf][1]));
        }

        __syncthreads();                          // all warps done with buffer i&1
        if (i + 2 < NC) stage(i + 2);             // refill; overlaps compute(i+1)
    }

    // ---- epilogue: +bias, optional ReLU, fp32 float2 stores ----
    float* ob = OUT_S ? (float*)g_hidden : gout;
    const float* brow = bias + (size_t)cat * 1024 + n0;
    float2 bb[8];
    #pragma unroll
    for (int nf = 0; nf < 8; nf++)
        bb[nf] = *(const float2*)(brow + wn + nf * 8 + lr * 2);

    const int batch = s_cb[wid & 1];              // warp tile = one 32-row slab
    #pragma unroll
    for (int mf = 0; mf < 2; mf++) {
        const int r0 = mf * 16 + lg;              // row within slab
        float* o0 = ob + ((size_t)batch * T_ + r0    ) * 1024 + n0;
        float* o1 = ob + ((size_t)batch * T_ + r0 + 8) * 1024 + n0;
        #pragma unroll
        for (int nf = 0; nf < 8; nf++) {
            const int col = wn + nf * 8 + lr * 2;
            float2 v0, v1;
            v0.x = acc[mf][nf][0] + bb[nf].x;
            v0.y = acc[mf][nf][1] + bb[nf].y;
            v1.x = acc[mf][nf][2] + bb[nf].x;
            v1.y = acc[mf][nf][3] + bb[nf].y;
            if (RELU) {
                v0.x = fmaxf(v0.x, 0.f); v0.y = fmaxf(v0.y, 0.f);
                v1.x = fmaxf(v1.x, 0.f); v1.y = fmaxf(v1.y, 0.f);
            }
            *(float2*)(o0 + col) = v0;
            *(float2*)(o1 + col) = v1;
        }
    }
}

// ---------------------------------------------------------------------------
extern "C" void kernel_launch(void* const* d_in, const int* in_sizes, int n_in,
                              void* d_out, int out_size) {
    const float* x   = (const float*)d_in[0];
    const int*   cat = (const int*)  d_in[1];
    const float* W1  = (const float*)d_in[2];
    const float* b1  = (const float*)d_in[3];
    const float* W2  = (const float*)d_in[4];
    const float* b2  = (const float*)d_in[5];
    float*       out = (float*)d_out;

    cudaFuncSetAttribute(catmlp_gemm<1536, true,  false, true >,
                         cudaFuncAttributeMaxDynamicSharedMemorySize, SMEM_REQ);
    cudaFuncSetAttribute(catmlp_gemm<1024, false, true,  false>,
                         cudaFuncAttributeMaxDynamicSharedMemorySize, SMEM_REQ);

    dim3 grid(MAXCH, 1024 / BN);
    catmlp_gemm<1536, true,  false, true ><<<grid, NT, SMEM_REQ>>>(x,  W1, b1, cat, nullptr);
    catmlp_gemm<1024, false, true,  false><<<grid, NT, SMEM_REQ>>>(nullptr, W2, b2, cat, out);
}